// round 1
// baseline (speedup 1.0000x reference)
#include <cuda_runtime.h>
#include <stdint.h>

#define NPG   256
#define FDIM  128
#define EPG   4096
#define KTOP  30
#define STR   33   // padded row stride (floats) for 32-wide node rows

// ---- dynamic smem byte offsets ----
#define OFF_Z1    0            // h1 / y0     256*33*4 = 33792
#define OFF_Z2    33792        // h2 / y1
#define OFF_Z3    67584        // h3 / y2
#define OFF_Z4    101376       // h4 / y3     256*4 = 1024
#define OFF_P     102400       // pooled scratch 33792
#define OFF_W1    136192       // 32x32 f32
#define OFF_W2    140288
#define OFF_W3    144384       // 32 f32 (pad 128B)
#define OFF_B0    144512
#define OFF_B1    144640
#define OFF_B2    144768
#define OFF_B3    144896
#define OFF_DINV  145024       // 256 f32
#define OFF_CSR   146048       // 4096 u16
#define OFF_COFF  154240       // 257 u32
#define OFF_CNT   155268       // 256 u32
#define OFF_KEYS  156296       // 256 u64 (8-aligned)
#define OFF_CW1   158344       // 16*97 f32 = 6208
#define OFF_CW2   164552       // 32*16*5 f32 = 10240
#define OFF_CB1   174792       // 16 f32
#define OFF_CB2   174856       // 32 f32
#define OFF_OB    174984       // 2 f32
#define OFF_OW    174992       // 352*2 f32 = 2816
#define OFF_O1    177808       // 16*30 f32
#define OFF_PM    179728       // 16*15 f32
#define OFF_O2    180688       // 32*11 f32 -> end 182096
#define SMEM_TOTAL 182096
// layer-0 staging aliases the (not-yet-used) Z2/Z3 regions:
#define OFF_W0S   33792        // 128*32 f32 = 16384
#define OFF_SF    50176        // 64*129 f32 = 33024 (ends 83200 < 101376)

extern __shared__ unsigned char smem_raw[];

__device__ __forceinline__ void gemm32(const float* __restrict__ Zin,
                                       float* __restrict__ Zout,
                                       const float* __restrict__ Ws, int tid)
{
    // 256 rows x 32 cols; thread = (row = tid>>1, 16-col half = tid&1)
    int v = tid >> 1;
    int half = tid & 1;
    const float4* W4 = (const float4*)Ws;   // W stored [32][32]
    float acc[16];
#pragma unroll
    for (int i = 0; i < 16; i++) acc[i] = 0.f;
#pragma unroll
    for (int k = 0; k < 32; k++) {
        float a = Zin[v * STR + k];
#pragma unroll
        for (int j = 0; j < 4; j++) {
            float4 w = W4[k * 8 + half * 4 + j];
            acc[j*4+0] = fmaf(a, w.x, acc[j*4+0]);
            acc[j*4+1] = fmaf(a, w.y, acc[j*4+1]);
            acc[j*4+2] = fmaf(a, w.z, acc[j*4+2]);
            acc[j*4+3] = fmaf(a, w.w, acc[j*4+3]);
        }
    }
    float* o = Zout + v * STR + half * 16;
#pragma unroll
    for (int i = 0; i < 16; i++) o[i] = acc[i];
}

// pooled[v] = y[v] + sum_{incoming src} y[src]; h = tanh((pooled + b) * dinv)
__device__ __forceinline__ void scatter_act32(float* __restrict__ Zy,
                                              float* __restrict__ P,
                                              const unsigned* __restrict__ OFFA,
                                              const unsigned short* __restrict__ CSR,
                                              const float* __restrict__ bias,
                                              const float* __restrict__ dinv, int tid)
{
    int w = tid >> 5, lane = tid & 31;    // 16 warps x 16 nodes, lane = channel
    for (int v = w * 16; v < w * 16 + 16; v++) {
        float sum = Zy[v * STR + lane];
        unsigned o0 = OFFA[v], o1 = OFFA[v + 1];
        for (unsigned i = o0; i < o1; i++) {
            int s = CSR[i];
            sum += Zy[s * STR + lane];   // conflict-free: consecutive banks
        }
        P[v * STR + lane] = sum;
    }
    __syncthreads();
    for (int i = tid; i < 256 * 32; i += 512) {
        int v = i >> 5, c = i & 31;
        Zy[v * STR + c] = tanhf((P[v * STR + c] + bias[c]) * dinv[v]);
    }
    __syncthreads();
}

__global__ void __launch_bounds__(512, 1)
dgcnn_kernel(const float* __restrict__ feat,
             const int* __restrict__ src, const int* __restrict__ dst,
             const int* __restrict__ degs,
             const float* __restrict__ W0, const float* __restrict__ b0,
             const float* __restrict__ W1, const float* __restrict__ b1,
             const float* __restrict__ W2, const float* __restrict__ b2,
             const float* __restrict__ W3, const float* __restrict__ b3,
             const float* __restrict__ cw1, const float* __restrict__ cb1,
             const float* __restrict__ cw2, const float* __restrict__ cb2,
             const float* __restrict__ ow, const float* __restrict__ ob,
             float* __restrict__ out)
{
    const int g   = blockIdx.x;
    const int tid = threadIdx.x;

    float* Z1 = (float*)(smem_raw + OFF_Z1);
    float* Z2 = (float*)(smem_raw + OFF_Z2);
    float* Z3 = (float*)(smem_raw + OFF_Z3);
    float* Z4 = (float*)(smem_raw + OFF_Z4);
    float* P  = (float*)(smem_raw + OFF_P);
    float* W1s = (float*)(smem_raw + OFF_W1);
    float* W2s = (float*)(smem_raw + OFF_W2);
    float* W3s = (float*)(smem_raw + OFF_W3);
    float* B0s = (float*)(smem_raw + OFF_B0);
    float* B1s = (float*)(smem_raw + OFF_B1);
    float* B2s = (float*)(smem_raw + OFF_B2);
    float* B3s = (float*)(smem_raw + OFF_B3);
    float* DINV = (float*)(smem_raw + OFF_DINV);
    unsigned short* CSR = (unsigned short*)(smem_raw + OFF_CSR);
    unsigned* COFF = (unsigned*)(smem_raw + OFF_COFF);
    unsigned* CNT  = (unsigned*)(smem_raw + OFF_CNT);
    unsigned long long* KEYS = (unsigned long long*)(smem_raw + OFF_KEYS);
    float* CW1s = (float*)(smem_raw + OFF_CW1);
    float* CW2s = (float*)(smem_raw + OFF_CW2);
    float* CB1s = (float*)(smem_raw + OFF_CB1);
    float* CB2s = (float*)(smem_raw + OFF_CB2);
    float* OBs  = (float*)(smem_raw + OFF_OB);
    float* OWs  = (float*)(smem_raw + OFF_OW);
    float* O1s  = (float*)(smem_raw + OFF_O1);
    float* PMs  = (float*)(smem_raw + OFF_PM);
    float* O2s  = (float*)(smem_raw + OFF_O2);
    float* W0s = (float*)(smem_raw + OFF_W0S);   // alias in Z2
    float* SF  = (float*)(smem_raw + OFF_SF);    // alias in Z2/Z3

    // ---- Phase A: load small weights, degs, build CSR ----
    for (int i = tid; i < 1024; i += 512) { W1s[i] = W1[i]; W2s[i] = W2[i]; }
    for (int i = tid; i < 4096; i += 512) W0s[i] = W0[i];
    if (tid < 32) { W3s[tid] = W3[tid]; B0s[tid] = b0[tid]; B1s[tid] = b1[tid]; B2s[tid] = b2[tid]; }
    if (tid == 0) B3s[0] = b3[0];
    for (int i = tid; i < 16 * 97; i += 512) CW1s[i] = cw1[i];
    for (int i = tid; i < 32 * 16 * 5; i += 512) CW2s[i] = cw2[i];
    if (tid < 16) CB1s[tid] = cb1[tid];
    if (tid < 32) CB2s[tid] = cb2[tid];
    for (int i = tid; i < 704; i += 512) OWs[i] = ow[i];
    if (tid < 2) OBs[tid] = ob[tid];

    int indeg = 0;
    if (tid < 256) {
        indeg = degs[g * NPG + tid];
        DINV[tid] = 1.0f / (float)(indeg + 1);
        COFF[tid] = (unsigned)indeg;
        CNT[tid]  = 0u;
    }
    __syncthreads();
    // inclusive scan of indeg (Hillis-Steele, 8 steps)
    for (int d = 1; d < 256; d <<= 1) {
        unsigned t = 0;
        if (tid < 256 && tid >= d) t = COFF[tid - d];
        __syncthreads();
        if (tid < 256 && tid >= d) COFF[tid] += t;
        __syncthreads();
    }
    unsigned myoff = 0;
    if (tid < 256) myoff = COFF[tid] - (unsigned)indeg;   // exclusive
    __syncthreads();
    if (tid < 256) COFF[tid] = myoff;
    if (tid == 0) COFF[256] = EPG;
    __syncthreads();
    // bucket-fill CSR (src list per dst); graph g's edges are [g*4096, g*4096+4096)
    for (int e = tid; e < EPG; e += 512) {
        int s = src[g * EPG + e] - g * NPG;
        int d = dst[g * EPG + e] - g * NPG;
        unsigned p = atomicAdd(&CNT[d], 1u);
        CSR[COFF[d] + p] = (unsigned short)s;
    }

    // ---- Phase B: layer 0 GEMM  y0 = feat_tile @ W0 -> Z1 ----
    const float4* feat4 = (const float4*)feat;
    for (int c = 0; c < 4; c++) {        // 4 chunks of 64 rows
        __syncthreads();                 // protect SF reuse (covers CSR fill on c=0)
        for (int i = tid; i < 2048; i += 512) {
            int r = i >> 5, k4 = i & 31;
            float4 v = feat4[(size_t)(g * NPG + c * 64 + r) * 32 + k4];
            float* p = SF + r * 129 + k4 * 4;
            p[0] = v.x; p[1] = v.y; p[2] = v.z; p[3] = v.w;
        }
        __syncthreads();
        int r  = tid >> 3;   // 0..63
        int cg = tid & 7;    // 4-col group
        float a0 = 0.f, a1 = 0.f, a2 = 0.f, a3 = 0.f;
        const float4* W04 = (const float4*)W0s;
#pragma unroll 4
        for (int k = 0; k < 128; k++) {
            float a = SF[r * 129 + k];
            float4 w = W04[k * 8 + cg];
            a0 = fmaf(a, w.x, a0); a1 = fmaf(a, w.y, a1);
            a2 = fmaf(a, w.z, a2); a3 = fmaf(a, w.w, a3);
        }
        float* zr = Z1 + (c * 64 + r) * STR + cg * 4;
        zr[0] = a0; zr[1] = a1; zr[2] = a2; zr[3] = a3;
    }
    __syncthreads();

    // ---- layers 0..2 aggregation + activation; layers 1,2 GEMMs ----
    scatter_act32(Z1, P, COFF, CSR, B0s, DINV, tid);            // h1 in Z1
    gemm32(Z1, Z2, W1s, tid); __syncthreads();
    scatter_act32(Z2, P, COFF, CSR, B1s, DINV, tid);            // h2 in Z2
    gemm32(Z2, Z3, W2s, tid); __syncthreads();
    scatter_act32(Z3, P, COFF, CSR, B2s, DINV, tid);            // h3 in Z3

    // ---- layer 3 (dout = 1) ----
    if (tid < 256) {
        float s = 0.f;
#pragma unroll
        for (int k = 0; k < 32; k++) s = fmaf(Z3[tid * STR + k], W3s[k], s);
        Z4[tid] = s;
    }
    __syncthreads();
    if (tid < 256) {
        float sum = Z4[tid];
        unsigned o0 = COFF[tid], o1 = COFF[tid + 1];
        for (unsigned i = o0; i < o1; i++) sum += Z4[CSR[i]];
        P[tid] = sum;
    }
    __syncthreads();
    if (tid < 256) Z4[tid] = tanhf((P[tid] + B3s[0]) * DINV[tid]);
    __syncthreads();

    // ---- sortpool: bitonic sort 256 keys (desc value, asc index on ties) ----
    if (tid < 256) {
        unsigned bits = __float_as_uint(Z4[tid]);
        unsigned uv = (bits & 0x80000000u) ? ~bits : (bits | 0x80000000u); // asc order map
        unsigned kv = ~uv;                                                // descending
        KEYS[tid] = ((unsigned long long)kv << 32) | (unsigned)tid;
    }
    __syncthreads();
    for (int k = 2; k <= 256; k <<= 1) {
        for (int j = k >> 1; j > 0; j >>= 1) {
            if (tid < 256) {
                int ixj = tid ^ j;
                if (ixj > tid) {
                    bool up = ((tid & k) == 0);
                    unsigned long long a = KEYS[tid], b = KEYS[ixj];
                    if ((a > b) == up) { KEYS[tid] = b; KEYS[ixj] = a; }
                }
            }
            __syncthreads();
        }
    }

    // ---- conv1 (97-tap dot over concat features), relu ----
    for (int t = tid; t < 16 * KTOP; t += 512) {
        int c = t / KTOP, k = t % KTOP;
        int idx = (int)(KEYS[k] & 0xFFu);
        const float* wr = CW1s + c * 97;
        float s = CB1s[c];
        for (int d = 0; d < 32; d++) s = fmaf(Z1[idx * STR + d], wr[d], s);
        for (int d = 0; d < 32; d++) s = fmaf(Z2[idx * STR + d], wr[32 + d], s);
        for (int d = 0; d < 32; d++) s = fmaf(Z3[idx * STR + d], wr[64 + d], s);
        s = fmaf(Z4[idx], wr[96], s);
        O1s[c * KTOP + k] = fmaxf(s, 0.f);
    }
    __syncthreads();
    // maxpool(2,2) -> [16][15]
    for (int t = tid; t < 16 * 15; t += 512) {
        int c = t / 15, j = t % 15;
        PMs[c * 15 + j] = fmaxf(O1s[c * KTOP + 2 * j], O1s[c * KTOP + 2 * j + 1]);
    }
    __syncthreads();
    // conv2 (k=5) -> [32][11], relu
    for (int t = tid; t < 32 * 11; t += 512) {
        int c2 = t / 11, tt = t % 11;
        float s = CB2s[c2];
        for (int c1 = 0; c1 < 16; c1++) {
            const float* w = CW2s + (c2 * 16 + c1) * 5;
            const float* p = PMs + c1 * 15 + tt;
#pragma unroll
            for (int kk = 0; kk < 5; kk++) s = fmaf(p[kk], w[kk], s);
        }
        O2s[c2 * 11 + tt] = fmaxf(s, 0.f);
    }
    __syncthreads();
    // dense [352 -> 2], relu(relu(x)) == relu(x)
    if (tid < 64) {
        int o = tid >> 5, lane = tid & 31;
        float s = 0.f;
        for (int i = lane; i < 352; i += 32) s = fmaf(O2s[i], OWs[i * 2 + o], s);
#pragma unroll
        for (int d = 16; d > 0; d >>= 1) s += __shfl_down_sync(0xffffffffu, s, d);
        if (lane == 0) out[g * 2 + o] = fmaxf(s + OBs[o], 0.f);
    }
}

extern "C" void kernel_launch(void* const* d_in, const int* in_sizes, int n_in,
                              void* d_out, int out_size)
{
    const float *feat, *W0, *b0, *W1, *b1, *W2, *b2, *W3, *b3;
    const float *cw1, *cb1, *cw2, *cb2, *ow, *ob;
    const int *src, *dst, *degs;

    if (n_in >= 2 && in_sizes[1] == 1048576) {
        // dict order: node_feat, src, dst, degs, W0,b0,...,out_b
        feat = (const float*)d_in[0];
        src  = (const int*)d_in[1];
        dst  = (const int*)d_in[2];
        degs = (const int*)d_in[3];
        W0 = (const float*)d_in[4];  b0 = (const float*)d_in[5];
        W1 = (const float*)d_in[6];  b1 = (const float*)d_in[7];
        W2 = (const float*)d_in[8];  b2 = (const float*)d_in[9];
        W3 = (const float*)d_in[10]; b3 = (const float*)d_in[11];
        cw1 = (const float*)d_in[12]; cb1 = (const float*)d_in[13];
        cw2 = (const float*)d_in[14]; cb2 = (const float*)d_in[15];
        ow  = (const float*)d_in[16]; ob  = (const float*)d_in[17];
    } else {
        // reference-signature order
        feat = (const float*)d_in[0];
        W0 = (const float*)d_in[1];  b0 = (const float*)d_in[2];
        W1 = (const float*)d_in[3];  b1 = (const float*)d_in[4];
        W2 = (const float*)d_in[5];  b2 = (const float*)d_in[6];
        W3 = (const float*)d_in[7];  b3 = (const float*)d_in[8];
        cw1 = (const float*)d_in[9];  cb1 = (const float*)d_in[10];
        cw2 = (const float*)d_in[11]; cb2 = (const float*)d_in[12];
        ow  = (const float*)d_in[13]; ob  = (const float*)d_in[14];
        src  = (const int*)d_in[15];
        dst  = (const int*)d_in[16];
        degs = (const int*)d_in[17];
    }

    cudaFuncSetAttribute(dgcnn_kernel,
                         cudaFuncAttributeMaxDynamicSharedMemorySize, SMEM_TOTAL);
    dgcnn_kernel<<<256, 512, SMEM_TOTAL>>>(
        feat, src, dst, degs,
        W0, b0, W1, b1, W2, b2, W3, b3,
        cw1, cb1, cw2, cb2, ow, ob,
        (float*)d_out);
}

// round 2
// speedup vs baseline: 1.0346x; 1.0346x over previous
#include <cuda_runtime.h>
#include <stdint.h>

#define NPG   256
#define FDIM  128
#define EPG   4096
#define KTOP  30
#define STR   34   // padded row stride (floats), even -> 8B-aligned float2 rows

// ---- dynamic smem byte offsets ----
#define ZBYTES    34816        // 256*34*4
#define OFF_Z1    0
#define OFF_Z2    34816
#define OFF_Z3    69632
#define OFF_P     104448
#define OFF_Z4    139264       // 256 f32
#define OFF_W1    140288       // 32x32 f32
#define OFF_W2    144384
#define OFF_W3    148480       // 32 f32
#define OFF_B0    148608
#define OFF_B1    148736
#define OFF_B2    148864
#define OFF_B3    148992
#define OFF_DINV  149120       // 256 f32
#define OFF_CSR   150144       // 4096 u16 (premultiplied src*STR)
#define OFF_COFF  158336       // 257 u32 (pad to 1056)
#define OFF_CNT   159392       // 256 u32
#define OFF_WS    160416       // 16 u32 warp-scan partials
#define OFF_KEYS  160480       // 256 u64
#define OFF_CW1   162528       // 16*97 f32
#define OFF_CW2   168736       // 32*16*5 f32
#define OFF_CB1   178976
#define OFF_CB2   179040
#define OFF_OB    179168
#define OFF_OW    179184       // 352*2 f32
#define OFF_O1    182000       // 16*30 f32
#define OFF_PM    183920       // 16*15 f32
#define OFF_O2    184880       // 32*11 f32
#define OFF_W0S   186288       // 128*32 f32
#define SMEM_TOTAL 202672
// layer-0 feat staging aliases Z2+Z3 (dead at that point): 128 rows x 132 f32
#define OFF_SF    34816

extern __shared__ unsigned char smem_raw[];

// packed dual-FMA: d = a*b + d  (2 fp32 lanes per instruction)
__device__ __forceinline__ void ffma2(float2& d, const float2 a, const float2 b) {
    asm("fma.rn.f32x2 %0, %1, %2, %0;"
        : "+l"(reinterpret_cast<unsigned long long&>(d))
        : "l"(reinterpret_cast<const unsigned long long&>(const_cast<float2&>(a))),
          "l"(reinterpret_cast<const unsigned long long&>(const_cast<float2&>(b))));
}
__device__ __forceinline__ float2 dup2(float a) { return make_float2(a, a); }

// accurate fast tanh (Eigen rational approx, ~1 ulp-level for fp32)
__device__ __forceinline__ float fast_tanh(float x) {
    x = fminf(fmaxf(x, -9.f), 9.f);
    float x2 = x * x;
    float p = fmaf(x2, -2.76076847742355e-16f, 2.00018790482477e-13f);
    p = fmaf(x2, p, -8.60467152213735e-11f);
    p = fmaf(x2, p, 5.12229709037114e-08f);
    p = fmaf(x2, p, 1.48572235717979e-05f);
    p = fmaf(x2, p, 6.37261928875436e-04f);
    p = fmaf(x2, p, 4.89352455891786e-03f);
    p *= x;
    float q = fmaf(x2, 1.19825839466702e-06f, 1.18534705686654e-04f);
    q = fmaf(x2, q, 2.26843463243900e-03f);
    q = fmaf(x2, q, 4.89352518554385e-03f);
    return __fdividef(p, q);
}

// 256x32 @ 32x32 -> P, using FFMA2. thread = (row = tid>>1, 16-col half = tid&1)
__device__ __forceinline__ void gemm32_f2(const float* __restrict__ Zin,
                                          float* __restrict__ Pout,
                                          const float* __restrict__ Ws, int tid)
{
    int v = tid >> 1;
    int half = tid & 1;
    const float4* W4 = (const float4*)Ws;
    const float* arow = Zin + v * STR;
    float2 acc[8];
#pragma unroll
    for (int j = 0; j < 8; j++) acc[j] = make_float2(0.f, 0.f);
#pragma unroll
    for (int k = 0; k < 32; k++) {
        float2 aa = dup2(arow[k]);
#pragma unroll
        for (int j = 0; j < 4; j++) {
            float4 w = W4[k * 8 + half * 4 + j];
            ffma2(acc[j * 2 + 0], aa, make_float2(w.x, w.y));
            ffma2(acc[j * 2 + 1], aa, make_float2(w.z, w.w));
        }
    }
    float2* o = (float2*)(Pout + v * STR + half * 16);
#pragma unroll
    for (int j = 0; j < 8; j++) o[j] = acc[j];
}

// pooled[v] = P[v] + sum_{incoming} P[src]; Zl[v] = tanh((pooled + b) * dinv[v])
// CSR entries are premultiplied by STR. 4-way ILP to break the LDS chain.
__device__ __forceinline__ void scatter_act(const float* __restrict__ P,
                                            float* __restrict__ Zl,
                                            const unsigned* __restrict__ OFFA,
                                            const unsigned short* __restrict__ CSRp,
                                            const float* __restrict__ bias,
                                            const float* __restrict__ dinv, int tid)
{
    int w = tid >> 5, lane = tid & 31;
    float bl = bias[lane];
    for (int v = w * 16; v < w * 16 + 16; v++) {
        unsigned o0 = OFFA[v], o1 = OFFA[v + 1];
        float s0 = P[v * STR + lane], s1 = 0.f, s2 = 0.f, s3 = 0.f;
        unsigned i = o0;
        for (; i + 4 <= o1; i += 4) {
            unsigned a = CSRp[i], b = CSRp[i + 1], c = CSRp[i + 2], d = CSRp[i + 3];
            s0 += P[a + lane];
            s1 += P[b + lane];
            s2 += P[c + lane];
            s3 += P[d + lane];
        }
        for (; i < o1; i++) s0 += P[CSRp[i] + lane];
        float sum = (s0 + s1) + (s2 + s3);
        Zl[v * STR + lane] = fast_tanh((sum + bl) * dinv[v]);
    }
}

__global__ void __launch_bounds__(512, 1)
dgcnn_kernel(const float* __restrict__ feat,
             const int* __restrict__ src, const int* __restrict__ dst,
             const int* __restrict__ degs,
             const float* __restrict__ W0, const float* __restrict__ b0,
             const float* __restrict__ W1, const float* __restrict__ b1,
             const float* __restrict__ W2, const float* __restrict__ b2,
             const float* __restrict__ W3, const float* __restrict__ b3,
             const float* __restrict__ cw1, const float* __restrict__ cb1,
             const float* __restrict__ cw2, const float* __restrict__ cb2,
             const float* __restrict__ ow, const float* __restrict__ ob,
             float* __restrict__ out)
{
    const int g   = blockIdx.x;
    const int tid = threadIdx.x;

    float* Z1 = (float*)(smem_raw + OFF_Z1);
    float* Z2 = (float*)(smem_raw + OFF_Z2);
    float* Z3 = (float*)(smem_raw + OFF_Z3);
    float* Z4 = (float*)(smem_raw + OFF_Z4);
    float* P  = (float*)(smem_raw + OFF_P);
    float* W1s = (float*)(smem_raw + OFF_W1);
    float* W2s = (float*)(smem_raw + OFF_W2);
    float* W3s = (float*)(smem_raw + OFF_W3);
    float* B0s = (float*)(smem_raw + OFF_B0);
    float* B1s = (float*)(smem_raw + OFF_B1);
    float* B2s = (float*)(smem_raw + OFF_B2);
    float* B3s = (float*)(smem_raw + OFF_B3);
    float* DINV = (float*)(smem_raw + OFF_DINV);
    unsigned short* CSRp = (unsigned short*)(smem_raw + OFF_CSR);
    unsigned* COFF = (unsigned*)(smem_raw + OFF_COFF);
    unsigned* CNT  = (unsigned*)(smem_raw + OFF_CNT);
    unsigned* WS   = (unsigned*)(smem_raw + OFF_WS);
    unsigned long long* KEYS = (unsigned long long*)(smem_raw + OFF_KEYS);
    float* CW1s = (float*)(smem_raw + OFF_CW1);
    float* CW2s = (float*)(smem_raw + OFF_CW2);
    float* CB1s = (float*)(smem_raw + OFF_CB1);
    float* CB2s = (float*)(smem_raw + OFF_CB2);
    float* OBs  = (float*)(smem_raw + OFF_OB);
    float* OWs  = (float*)(smem_raw + OFF_OW);
    float* O1s  = (float*)(smem_raw + OFF_O1);
    float* PMs  = (float*)(smem_raw + OFF_PM);
    float* O2s  = (float*)(smem_raw + OFF_O2);
    float* W0s  = (float*)(smem_raw + OFF_W0S);
    float* SF   = (float*)(smem_raw + OFF_SF);   // alias of Z2+Z3 during layer 0

    // ---- Phase A: load weights, degs; warp-scan offsets ----
    for (int i = tid; i < 1024; i += 512) { W1s[i] = W1[i]; W2s[i] = W2[i]; }
    for (int i = tid; i < 4096; i += 512) W0s[i] = W0[i];
    if (tid < 32) { W3s[tid] = W3[tid]; B0s[tid] = b0[tid]; B1s[tid] = b1[tid]; B2s[tid] = b2[tid]; }
    if (tid == 0) B3s[0] = b3[0];
    for (int i = tid; i < 16 * 97; i += 512) CW1s[i] = cw1[i];
    for (int i = tid; i < 32 * 16 * 5; i += 512) CW2s[i] = cw2[i];
    if (tid < 16) CB1s[tid] = cb1[tid];
    if (tid < 32) CB2s[tid] = cb2[tid];
    for (int i = tid; i < 704; i += 512) OWs[i] = ow[i];
    if (tid < 2) OBs[tid] = ob[tid];

    int indeg = 0;
    unsigned xincl = 0;
    if (tid < 256) {
        indeg = degs[g * NPG + tid];
        DINV[tid] = 1.0f / (float)(indeg + 1);
        CNT[tid]  = 0u;
        xincl = (unsigned)indeg;
#pragma unroll
        for (int d = 1; d < 32; d <<= 1) {
            unsigned t = __shfl_up_sync(0xffffffffu, xincl, d);
            if ((tid & 31) >= d) xincl += t;
        }
        if ((tid & 31) == 31) WS[tid >> 5] = xincl;
    }
    __syncthreads();
    if (tid == 0) {
        unsigned run = 0;
#pragma unroll
        for (int w = 0; w < 8; w++) { unsigned t = WS[w]; WS[w] = run; run += t; }
    }
    __syncthreads();
    if (tid < 256) COFF[tid] = xincl + WS[tid >> 5] - (unsigned)indeg;   // exclusive
    if (tid == 0) COFF[256] = EPG;
    __syncthreads();

    // bucket-fill CSR (premultiplied src*STR), int4 edge loads
    {
        const int gbase = g * NPG;
        const int4* s4 = (const int4*)(src + g * EPG);
        const int4* d4 = (const int4*)(dst + g * EPG);
        for (int e = tid; e < EPG / 4; e += 512) {
            int4 S = s4[e], D = d4[e];
            {
                int dl = D.x - gbase; unsigned p = atomicAdd(&CNT[dl], 1u);
                CSRp[COFF[dl] + p] = (unsigned short)((S.x - gbase) * STR);
            }
            {
                int dl = D.y - gbase; unsigned p = atomicAdd(&CNT[dl], 1u);
                CSRp[COFF[dl] + p] = (unsigned short)((S.y - gbase) * STR);
            }
            {
                int dl = D.z - gbase; unsigned p = atomicAdd(&CNT[dl], 1u);
                CSRp[COFF[dl] + p] = (unsigned short)((S.z - gbase) * STR);
            }
            {
                int dl = D.w - gbase; unsigned p = atomicAdd(&CNT[dl], 1u);
                CSRp[COFF[dl] + p] = (unsigned short)((S.w - gbase) * STR);
            }
        }
    }

    // ---- layer 0 GEMM: feat @ W0 -> P (2 chunks of 128 rows) ----
    const float4* feat4 = (const float4*)feat;
    for (int c = 0; c < 2; c++) {
        __syncthreads();   // protects SF reuse; first pass also fences W0s load
        for (int i = tid; i < 4096; i += 512) {
            int r = i >> 5, k4 = i & 31;
            float4 v = feat4[(size_t)(g * NPG + c * 128 + r) * 32 + k4];
            *(float4*)(SF + r * 132 + k4 * 4) = v;
        }
        __syncthreads();
        int r = tid >> 2, cg = tid & 3;         // 8 cols per thread
        const float* ar = SF + r * 132;
        const float4* W04 = (const float4*)W0s;
        float2 a0 = make_float2(0.f, 0.f), a1 = a0, a2 = a0, a3 = a0;
#pragma unroll 8
        for (int k = 0; k < 128; k++) {
            float2 aa = dup2(ar[k]);
            float4 w0 = W04[k * 8 + cg * 2];
            float4 w1 = W04[k * 8 + cg * 2 + 1];
            ffma2(a0, aa, make_float2(w0.x, w0.y));
            ffma2(a1, aa, make_float2(w0.z, w0.w));
            ffma2(a2, aa, make_float2(w1.x, w1.y));
            ffma2(a3, aa, make_float2(w1.z, w1.w));
        }
        float2* o = (float2*)(P + (c * 128 + r) * STR + cg * 8);
        o[0] = a0; o[1] = a1; o[2] = a2; o[3] = a3;
    }
    __syncthreads();   // CSR fill + layer-0 P complete

    // ---- GNN layers ----
    scatter_act(P, Z1, COFF, CSRp, B0s, DINV, tid); __syncthreads();
    gemm32_f2(Z1, P, W1s, tid);                     __syncthreads();
    scatter_act(P, Z2, COFF, CSRp, B1s, DINV, tid); __syncthreads();
    gemm32_f2(Z2, P, W2s, tid);                     __syncthreads();
    scatter_act(P, Z3, COFF, CSRp, B2s, DINV, tid); __syncthreads();

    // layer 3 (dout = 1): y3 stored at P[v*STR]
    if (tid < 256) {
        const float* zr = Z3 + tid * STR;
        float s0 = 0.f, s1 = 0.f, s2 = 0.f, s3 = 0.f;
#pragma unroll
        for (int k = 0; k < 32; k += 4) {
            s0 = fmaf(zr[k],     W3s[k],     s0);
            s1 = fmaf(zr[k + 1], W3s[k + 1], s1);
            s2 = fmaf(zr[k + 2], W3s[k + 2], s2);
            s3 = fmaf(zr[k + 3], W3s[k + 3], s3);
        }
        P[tid * STR] = (s0 + s1) + (s2 + s3);
    }
    __syncthreads();
    if (tid < 256) {
        unsigned o0 = COFF[tid], o1 = COFF[tid + 1];
        float s0 = P[tid * STR], s1 = 0.f, s2 = 0.f, s3 = 0.f;
        unsigned i = o0;
        for (; i + 4 <= o1; i += 4) {
            unsigned a = CSRp[i], b = CSRp[i + 1], c = CSRp[i + 2], d = CSRp[i + 3];
            s0 += P[a]; s1 += P[b]; s2 += P[c]; s3 += P[d];
        }
        for (; i < o1; i++) s0 += P[CSRp[i]];
        Z4[tid] = fast_tanh(((s0 + s1) + (s2 + s3) + B3s[0]) * DINV[tid]);
    }
    __syncthreads();

    // ---- sortpool: bitonic sort 256 keys (desc value, asc index ties) ----
    if (tid < 256) {
        unsigned bits = __float_as_uint(Z4[tid]);
        unsigned uv = (bits & 0x80000000u) ? ~bits : (bits | 0x80000000u);
        unsigned kv = ~uv;   // descending
        KEYS[tid] = ((unsigned long long)kv << 32) | (unsigned)tid;
    }
    __syncthreads();
    for (int k = 2; k <= 256; k <<= 1) {
        for (int j = k >> 1; j > 0; j >>= 1) {
            if (tid < 256) {
                int ixj = tid ^ j;
                if (ixj > tid) {
                    bool up = ((tid & k) == 0);
                    unsigned long long a = KEYS[tid], b = KEYS[ixj];
                    if ((a > b) == up) { KEYS[tid] = b; KEYS[ixj] = a; }
                }
            }
            __syncthreads();
        }
    }

    // ---- conv1 (97-tap), relu ----
    for (int t = tid; t < 16 * KTOP; t += 512) {
        int c = t / KTOP, k = t % KTOP;
        int idx = (int)(KEYS[k] & 0xFFu);
        const float* wr = CW1s + c * 97;
        float s = CB1s[c];
        const float2* z1r = (const float2*)(Z1 + idx * STR);
        const float2* z2r = (const float2*)(Z2 + idx * STR);
        const float2* z3r = (const float2*)(Z3 + idx * STR);
#pragma unroll
        for (int d = 0; d < 16; d++) {
            float2 z = z1r[d];
            s = fmaf(z.x, wr[2 * d], s); s = fmaf(z.y, wr[2 * d + 1], s);
        }
#pragma unroll
        for (int d = 0; d < 16; d++) {
            float2 z = z2r[d];
            s = fmaf(z.x, wr[32 + 2 * d], s); s = fmaf(z.y, wr[33 + 2 * d], s);
        }
#pragma unroll
        for (int d = 0; d < 16; d++) {
            float2 z = z3r[d];
            s = fmaf(z.x, wr[64 + 2 * d], s); s = fmaf(z.y, wr[65 + 2 * d], s);
        }
        s = fmaf(Z4[idx], wr[96], s);
        O1s[c * KTOP + k] = fmaxf(s, 0.f);
    }
    __syncthreads();
    // maxpool(2,2) -> [16][15]
    for (int t = tid; t < 16 * 15; t += 512) {
        int c = t / 15, j = t % 15;
        PMs[c * 15 + j] = fmaxf(O1s[c * KTOP + 2 * j], O1s[c * KTOP + 2 * j + 1]);
    }
    __syncthreads();
    // conv2 (k=5) -> [32][11], relu
    for (int t = tid; t < 32 * 11; t += 512) {
        int c2 = t / 11, tt = t % 11;
        float s = CB2s[c2];
#pragma unroll 4
        for (int c1 = 0; c1 < 16; c1++) {
            const float* w = CW2s + (c2 * 16 + c1) * 5;
            const float* p = PMs + c1 * 15 + tt;
#pragma unroll
            for (int kk = 0; kk < 5; kk++) s = fmaf(p[kk], w[kk], s);
        }
        O2s[c2 * 11 + tt] = fmaxf(s, 0.f);
    }
    __syncthreads();
    // dense [352 -> 2], relu
    if (tid < 64) {
        int o = tid >> 5, lane = tid & 31;
        float s = 0.f;
        for (int i = lane; i < 352; i += 32) s = fmaf(O2s[i], OWs[i * 2 + o], s);
#pragma unroll
        for (int d = 16; d > 0; d >>= 1) s += __shfl_down_sync(0xffffffffu, s, d);
        if (lane == 0) out[g * 2 + o] = fmaxf(s + OBs[o], 0.f);
    }
}

extern "C" void kernel_launch(void* const* d_in, const int* in_sizes, int n_in,
                              void* d_out, int out_size)
{
    const float *feat, *W0, *b0, *W1, *b1, *W2, *b2, *W3, *b3;
    const float *cw1, *cb1, *cw2, *cb2, *ow, *ob;
    const int *src, *dst, *degs;

    if (n_in >= 2 && in_sizes[1] == 1048576) {
        feat = (const float*)d_in[0];
        src  = (const int*)d_in[1];
        dst  = (const int*)d_in[2];
        degs = (const int*)d_in[3];
        W0 = (const float*)d_in[4];  b0 = (const float*)d_in[5];
        W1 = (const float*)d_in[6];  b1 = (const float*)d_in[7];
        W2 = (const float*)d_in[8];  b2 = (const float*)d_in[9];
        W3 = (const float*)d_in[10]; b3 = (const float*)d_in[11];
        cw1 = (const float*)d_in[12]; cb1 = (const float*)d_in[13];
        cw2 = (const float*)d_in[14]; cb2 = (const float*)d_in[15];
        ow  = (const float*)d_in[16]; ob  = (const float*)d_in[17];
    } else {
        feat = (const float*)d_in[0];
        W0 = (const float*)d_in[1];  b0 = (const float*)d_in[2];
        W1 = (const float*)d_in[3];  b1 = (const float*)d_in[4];
        W2 = (const float*)d_in[5];  b2 = (const float*)d_in[6];
        W3 = (const float*)d_in[7];  b3 = (const float*)d_in[8];
        cw1 = (const float*)d_in[9];  cb1 = (const float*)d_in[10];
        cw2 = (const float*)d_in[11]; cb2 = (const float*)d_in[12];
        ow  = (const float*)d_in[13]; ob  = (const float*)d_in[14];
        src  = (const int*)d_in[15];
        dst  = (const int*)d_in[16];
        degs = (const int*)d_in[17];
    }

    cudaFuncSetAttribute(dgcnn_kernel,
                         cudaFuncAttributeMaxDynamicSharedMemorySize, SMEM_TOTAL);
    dgcnn_kernel<<<256, 512, SMEM_TOTAL>>>(
        feat, src, dst, degs,
        W0, b0, W1, b1, W2, b2, W3, b3,
        cw1, cb1, cw2, cb2, ow, ob,
        (float*)d_out);
}

// round 3
// speedup vs baseline: 1.1800x; 1.1406x over previous
#include <cuda_runtime.h>
#include <stdint.h>

#define NPG   256
#define EPG   4096
#define KTOP  30
#define STR   34   // padded row stride (floats)

// ---- dynamic smem layout (bytes) ----
#define OFF_A     0            // 256*34*4 = 34816  (ping: h_l, feat staging, late scratch)
#define OFF_B     34816        // 34816             (pong: gemm output / pooled)
#define OFF_ACC   69632        // 16*256*4 = 16384  (conv1 accumulator; aliases W0 during layer0)
#define OFF_W0S   69632
#define OFF_CSR   86016        // 4096 u16 (premultiplied src*STR)
#define OFF_W1    94208        // 32x32 f32
#define OFF_W2    98304
#define OFF_CW1T  102400       // 97x16 f32 transposed = 6208
#define OFF_W3    108608       // 32 f32
#define OFF_B0    108736
#define OFF_B1    108864
#define OFF_B2    108992
#define OFF_B3    109120
#define OFF_DINV  109248       // 256 f32
#define OFF_COFF  110272       // 257 u32 (pad 1056)
#define OFF_CNT   111328       // 256 u32
#define OFF_WS    112352       // 16 u32
#define OFF_KEYS  112416       // 256 u64
#define OFF_CB1   114464       // 16 f32
#define SMEM_TOTAL 114528      // -> 114688 after 8KB granularity; 2 CTAs/SM fits 228KB

// late-phase scratch inside dead A (after offset 1024; A[0..255] holds h4)
#define SC_O1   1024           // 480 f32
#define SC_PM   2944           // 240 f32
#define SC_O2   3904           // 352 f32
#define SC_CW2  5312           // 2560 f32
#define SC_OW   15552          // 704 f32
#define SC_CB2  18368          // 32 f32
#define SC_OB   18496          // 2 f32

extern __shared__ unsigned char smem_raw[];

__device__ __forceinline__ void ffma2(float2& d, const float2 a, const float2 b) {
    asm("fma.rn.f32x2 %0, %1, %2, %0;"
        : "+l"(reinterpret_cast<unsigned long long&>(d))
        : "l"(reinterpret_cast<const unsigned long long&>(const_cast<float2&>(a))),
          "l"(reinterpret_cast<const unsigned long long&>(const_cast<float2&>(b))));
}
__device__ __forceinline__ float2 dup2(float a) { return make_float2(a, a); }

__device__ __forceinline__ float fast_tanh(float x) {
    x = fminf(fmaxf(x, -9.f), 9.f);
    float x2 = x * x;
    float p = fmaf(x2, -2.76076847742355e-16f, 2.00018790482477e-13f);
    p = fmaf(x2, p, -8.60467152213735e-11f);
    p = fmaf(x2, p, 5.12229709037114e-08f);
    p = fmaf(x2, p, 1.48572235717979e-05f);
    p = fmaf(x2, p, 6.37261928875436e-04f);
    p = fmaf(x2, p, 4.89352455891786e-03f);
    p *= x;
    float q = fmaf(x2, 1.19825839466702e-06f, 1.18534705686654e-04f);
    q = fmaf(x2, q, 2.26843463243900e-03f);
    q = fmaf(x2, q, 4.89352518554385e-03f);
    return __fdividef(p, q);
}

// ACC bank swizzle: rows c with bit3 set shift v by 16 banks
__device__ __forceinline__ int accidx(int c, int v) {
    return c * 256 + (v ^ ((c & 8) << 1));
}

// 256x32 @ 32x32 -> Pout (FFMA2); thread = (row v = tid>>1, 16-col half)
__device__ __forceinline__ void gemm32_f2(const float* __restrict__ Zin,
                                          float* __restrict__ Pout,
                                          const float* __restrict__ Ws, int tid)
{
    int v = tid >> 1, half = tid & 1;
    const float4* W4 = (const float4*)Ws;
    const float* arow = Zin + v * STR;
    float2 acc[8];
#pragma unroll
    for (int j = 0; j < 8; j++) acc[j] = make_float2(0.f, 0.f);
#pragma unroll
    for (int k = 0; k < 32; k++) {
        float2 aa = dup2(arow[k]);
#pragma unroll
        for (int j = 0; j < 4; j++) {
            float4 w = W4[k * 8 + half * 4 + j];
            ffma2(acc[j * 2 + 0], aa, make_float2(w.x, w.y));
            ffma2(acc[j * 2 + 1], aa, make_float2(w.z, w.w));
        }
    }
    float2* o = (float2*)(Pout + v * STR + half * 16);
#pragma unroll
    for (int j = 0; j < 8; j++) o[j] = acc[j];
}

// ACC[c][v] (+)= dot(Zl[v, 0:32], w[k][c])  for c in half*8..half*8+8
__device__ __forceinline__ void acc_pass(const float* __restrict__ Zl,
                                         float* __restrict__ ACC,
                                         const float* __restrict__ w, // [32][16]
                                         int tid, bool first)
{
    int v = tid >> 1, half = tid & 1;
    const float* ar = Zl + v * STR;
    float2 a0 = make_float2(0.f, 0.f), a1 = a0, a2 = a0, a3 = a0;
#pragma unroll
    for (int k = 0; k < 32; k++) {
        float2 aa = dup2(ar[k]);
        const float4 w0 = *(const float4*)(w + k * 16 + half * 8);
        const float4 w1 = *(const float4*)(w + k * 16 + half * 8 + 4);
        ffma2(a0, aa, make_float2(w0.x, w0.y));
        ffma2(a1, aa, make_float2(w0.z, w0.w));
        ffma2(a2, aa, make_float2(w1.x, w1.y));
        ffma2(a3, aa, make_float2(w1.z, w1.w));
    }
    float r[8] = {a0.x, a0.y, a1.x, a1.y, a2.x, a2.y, a3.x, a3.y};
    int cb = half * 8;
    if (first) {
#pragma unroll
        for (int j = 0; j < 8; j++) ACC[accidx(cb + j, v)] = r[j];
    } else {
#pragma unroll
        for (int j = 0; j < 8; j++) ACC[accidx(cb + j, v)] += r[j];
    }
}

// pooled = P[v] + sum_in P[src]; Zl = tanh((pooled+b)*dinv). CSR premult by STR.
__device__ __forceinline__ void scatter_act(const float* __restrict__ P,
                                            float* __restrict__ Zl,
                                            const unsigned* __restrict__ OFFA,
                                            const unsigned short* __restrict__ CSRp,
                                            const float* __restrict__ bias,
                                            const float* __restrict__ dinv, int tid)
{
    int w = tid >> 5, lane = tid & 31;
    float bl = bias[lane];
    for (int v = w * 16; v < w * 16 + 16; v++) {
        unsigned o0 = OFFA[v], o1 = OFFA[v + 1];
        float s0 = P[v * STR + lane], s1 = 0.f, s2 = 0.f, s3 = 0.f;
        unsigned i = o0;
        for (; i + 4 <= o1; i += 4) {
            unsigned a = CSRp[i], b = CSRp[i + 1], c = CSRp[i + 2], d = CSRp[i + 3];
            s0 += P[a + lane]; s1 += P[b + lane];
            s2 += P[c + lane]; s3 += P[d + lane];
        }
        for (; i < o1; i++) s0 += P[CSRp[i] + lane];
        Zl[v * STR + lane] = fast_tanh(((s0 + s1) + (s2 + s3) + bl) * dinv[v]);
    }
}

__global__ void __launch_bounds__(512, 2)
dgcnn_kernel(const float* __restrict__ feat,
             const int* __restrict__ src, const int* __restrict__ dst,
             const int* __restrict__ degs,
             const float* __restrict__ W0, const float* __restrict__ b0,
             const float* __restrict__ W1, const float* __restrict__ b1,
             const float* __restrict__ W2, const float* __restrict__ b2,
             const float* __restrict__ W3, const float* __restrict__ b3,
             const float* __restrict__ cw1, const float* __restrict__ cb1,
             const float* __restrict__ cw2, const float* __restrict__ cb2,
             const float* __restrict__ ow, const float* __restrict__ ob,
             float* __restrict__ out)
{
    const int g   = blockIdx.x;
    const int tid = threadIdx.x;

    float* A   = (float*)(smem_raw + OFF_A);
    float* B   = (float*)(smem_raw + OFF_B);
    float* ACC = (float*)(smem_raw + OFF_ACC);
    float* W0s = (float*)(smem_raw + OFF_W0S);
    unsigned short* CSRp = (unsigned short*)(smem_raw + OFF_CSR);
    float* W1s = (float*)(smem_raw + OFF_W1);
    float* W2s = (float*)(smem_raw + OFF_W2);
    float* CW1T = (float*)(smem_raw + OFF_CW1T);
    float* W3s = (float*)(smem_raw + OFF_W3);
    float* B0s = (float*)(smem_raw + OFF_B0);
    float* B1s = (float*)(smem_raw + OFF_B1);
    float* B2s = (float*)(smem_raw + OFF_B2);
    float* B3s = (float*)(smem_raw + OFF_B3);
    float* DINV = (float*)(smem_raw + OFF_DINV);
    unsigned* COFF = (unsigned*)(smem_raw + OFF_COFF);
    unsigned* CNT  = (unsigned*)(smem_raw + OFF_CNT);
    unsigned* WS   = (unsigned*)(smem_raw + OFF_WS);
    unsigned long long* KEYS = (unsigned long long*)(smem_raw + OFF_KEYS);
    float* CB1s = (float*)(smem_raw + OFF_CB1);
    // late-phase scratch in A
    float* O1s  = (float*)(smem_raw + OFF_A + SC_O1);
    float* PMs  = (float*)(smem_raw + OFF_A + SC_PM);
    float* O2s  = (float*)(smem_raw + OFF_A + SC_O2);
    float* CW2c = (float*)(smem_raw + OFF_A + SC_CW2);
    float* OWc  = (float*)(smem_raw + OFF_A + SC_OW);
    float* CB2c = (float*)(smem_raw + OFF_A + SC_CB2);
    float* OBc  = (float*)(smem_raw + OFF_A + SC_OB);

    // ---- Phase A: small weights, scan, CSR ----
    for (int i = tid; i < 1024; i += 512) { W1s[i] = W1[i]; W2s[i] = W2[i]; }
    for (int i = tid; i < 4096; i += 512) W0s[i] = W0[i];
    // transpose cw1 [16][97] -> CW1T[97][16]
    for (int i = tid; i < 97 * 16; i += 512) {
        int d = i >> 4, c = i & 15;
        CW1T[i] = cw1[c * 97 + d];
    }
    if (tid < 32) { W3s[tid] = W3[tid]; B0s[tid] = b0[tid]; B1s[tid] = b1[tid]; B2s[tid] = b2[tid]; }
    if (tid == 0) B3s[0] = b3[0];
    if (tid < 16) CB1s[tid] = cb1[tid];

    int indeg = 0;
    unsigned xincl = 0;
    if (tid < 256) {
        indeg = degs[g * NPG + tid];
        DINV[tid] = 1.0f / (float)(indeg + 1);
        CNT[tid]  = 0u;
        xincl = (unsigned)indeg;
#pragma unroll
        for (int d = 1; d < 32; d <<= 1) {
            unsigned t = __shfl_up_sync(0xffffffffu, xincl, d);
            if ((tid & 31) >= d) xincl += t;
        }
        if ((tid & 31) == 31) WS[tid >> 5] = xincl;
    }
    __syncthreads();
    if (tid == 0) {
        unsigned run = 0;
#pragma unroll
        for (int w = 0; w < 8; w++) { unsigned t = WS[w]; WS[w] = run; run += t; }
    }
    __syncthreads();
    if (tid < 256) COFF[tid] = xincl + WS[tid >> 5] - (unsigned)indeg;
    if (tid == 0) COFF[256] = EPG;
    __syncthreads();

    {
        const int gbase = g * NPG;
        const int4* s4 = (const int4*)(src + g * EPG);
        const int4* d4 = (const int4*)(dst + g * EPG);
        for (int e = tid; e < EPG / 4; e += 512) {
            int4 S = s4[e], D = d4[e];
            { int dl = D.x - gbase; unsigned p = atomicAdd(&CNT[dl], 1u);
              CSRp[COFF[dl] + p] = (unsigned short)((S.x - gbase) * STR); }
            { int dl = D.y - gbase; unsigned p = atomicAdd(&CNT[dl], 1u);
              CSRp[COFF[dl] + p] = (unsigned short)((S.y - gbase) * STR); }
            { int dl = D.z - gbase; unsigned p = atomicAdd(&CNT[dl], 1u);
              CSRp[COFF[dl] + p] = (unsigned short)((S.z - gbase) * STR); }
            { int dl = D.w - gbase; unsigned p = atomicAdd(&CNT[dl], 1u);
              CSRp[COFF[dl] + p] = (unsigned short)((S.w - gbase) * STR); }
        }
    }

    // ---- layer 0 GEMM: feat @ W0 -> B (4 chunks of 64 rows staged in A) ----
    const float4* feat4 = (const float4*)feat;
    for (int c = 0; c < 4; c++) {
        __syncthreads();
        for (int i = tid; i < 2048; i += 512) {
            int r = i >> 5, k4 = i & 31;
            *(float4*)(A + r * 132 + k4 * 4) =
                feat4[(size_t)(g * NPG + c * 64 + r) * 32 + k4];
        }
        __syncthreads();
        int r = tid >> 3, cg = tid & 7;    // 64 rows x 8 col-groups (4 cols each)
        const float* ar = A + r * 132;
        const float4* W04 = (const float4*)W0s;
        float2 a0 = make_float2(0.f, 0.f), a1 = a0;
#pragma unroll 8
        for (int k = 0; k < 128; k++) {
            float2 aa = dup2(ar[k]);
            float4 w = W04[k * 8 + cg];
            ffma2(a0, aa, make_float2(w.x, w.y));
            ffma2(a1, aa, make_float2(w.z, w.w));
        }
        float2* o = (float2*)(B + (c * 64 + r) * STR + cg * 4);
        o[0] = a0; o[1] = a1;
    }
    __syncthreads();

    // ---- GNN layers: B->A (h), ACC accumulate, A->B (gemm) ----
    scatter_act(B, A, COFF, CSRp, B0s, DINV, tid); __syncthreads();
    acc_pass(A, ACC, CW1T, tid, true);             // no barrier needed vs gemm (disjoint writes)
    gemm32_f2(A, B, W1s, tid);                     __syncthreads();
    scatter_act(B, A, COFF, CSRp, B1s, DINV, tid); __syncthreads();
    acc_pass(A, ACC, CW1T + 32 * 16, tid, false);
    gemm32_f2(A, B, W2s, tid);                     __syncthreads();
    scatter_act(B, A, COFF, CSRp, B2s, DINV, tid); __syncthreads();
    acc_pass(A, ACC, CW1T + 64 * 16, tid, false);

    // layer 3 (dout=1): y3 -> B[v*STR]   (reads A only; no barrier vs acc_pass)
    if (tid < 256) {
        const float* zr = A + tid * STR;
        float s0 = 0.f, s1 = 0.f, s2 = 0.f, s3 = 0.f;
#pragma unroll
        for (int k = 0; k < 32; k += 4) {
            s0 = fmaf(zr[k],     W3s[k],     s0);
            s1 = fmaf(zr[k + 1], W3s[k + 1], s1);
            s2 = fmaf(zr[k + 2], W3s[k + 2], s2);
            s3 = fmaf(zr[k + 3], W3s[k + 3], s3);
        }
        B[tid * STR] = (s0 + s1) + (s2 + s3);
    }
    __syncthreads();
    // h4 = tanh((y3 + scatter + b3)*dinv) -> A[0..255]
    if (tid < 256) {
        unsigned o0 = COFF[tid], o1 = COFF[tid + 1];
        float s0 = B[tid * STR], s1 = 0.f, s2 = 0.f, s3 = 0.f;
        unsigned i = o0;
        for (; i + 4 <= o1; i += 4) {
            unsigned a = CSRp[i], b = CSRp[i + 1], c = CSRp[i + 2], d = CSRp[i + 3];
            s0 += B[a]; s1 += B[b]; s2 += B[c]; s3 += B[d];
        }
        for (; i < o1; i++) s0 += B[CSRp[i]];
        A[tid] = fast_tanh(((s0 + s1) + (s2 + s3) + B3s[0]) * DINV[tid]);
    }
    __syncthreads();

    // keys + stage CNN-head weights into dead A scratch (disjoint regions)
    if (tid < 256) {
        unsigned bits = __float_as_uint(A[tid]);
        unsigned uv = (bits & 0x80000000u) ? ~bits : (bits | 0x80000000u);
        KEYS[tid] = ((unsigned long long)(~uv) << 32) | (unsigned)tid;
    }
    for (int i = tid; i < 2560; i += 512) CW2c[i] = cw2[i];
    for (int i = tid; i < 704; i += 512) OWc[i] = ow[i];
    if (tid < 32) CB2c[tid] = cb2[tid];
    if (tid < 2) OBc[tid] = ob[tid];
    __syncthreads();

    // bitonic sort 256 u64 keys (desc value, asc idx)
    for (int k = 2; k <= 256; k <<= 1) {
        for (int j = k >> 1; j > 0; j >>= 1) {
            if (tid < 256) {
                int ixj = tid ^ j;
                if (ixj > tid) {
                    bool up = ((tid & k) == 0);
                    unsigned long long a = KEYS[tid], b = KEYS[ixj];
                    if ((a > b) == up) { KEYS[tid] = b; KEYS[ixj] = a; }
                }
            }
            __syncthreads();
        }
    }

    // conv1 output from ACC (+ h4 term), relu
    if (tid < 480) {
        int c = tid & 15, k = tid >> 4;      // k = 0..29
        int idx = (int)(KEYS[k] & 0xFFu);
        float s = ACC[accidx(c, idx)] + A[idx] * CW1T[96 * 16 + c] + CB1s[c];
        O1s[c * KTOP + k] = fmaxf(s, 0.f);
    }
    __syncthreads();
    for (int t = tid; t < 16 * 15; t += 512) {
        int c = t / 15, j = t % 15;
        PMs[c * 15 + j] = fmaxf(O1s[c * KTOP + 2 * j], O1s[c * KTOP + 2 * j + 1]);
    }
    __syncthreads();
    for (int t = tid; t < 32 * 11; t += 512) {
        int c2 = t / 11, tt = t % 11;
        float s = CB2c[c2];
#pragma unroll 4
        for (int c1 = 0; c1 < 16; c1++) {
            const float* w = CW2c + (c2 * 16 + c1) * 5;
            const float* p = PMs + c1 * 15 + tt;
#pragma unroll
            for (int kk = 0; kk < 5; kk++) s = fmaf(p[kk], w[kk], s);
        }
        O2s[c2 * 11 + tt] = fmaxf(s, 0.f);
    }
    __syncthreads();
    if (tid < 64) {
        int o = tid >> 5, lane = tid & 31;
        float s = 0.f;
        for (int i = lane; i < 352; i += 32) s = fmaf(O2s[i], OWc[i * 2 + o], s);
#pragma unroll
        for (int d = 16; d > 0; d >>= 1) s += __shfl_down_sync(0xffffffffu, s, d);
        if (lane == 0) out[g * 2 + o] = fmaxf(s + OBc[o], 0.f);
    }
}

extern "C" void kernel_launch(void* const* d_in, const int* in_sizes, int n_in,
                              void* d_out, int out_size)
{
    const float *feat, *W0, *b0, *W1, *b1, *W2, *b2, *W3, *b3;
    const float *cw1, *cb1, *cw2, *cb2, *ow, *ob;
    const int *src, *dst, *degs;

    if (n_in >= 2 && in_sizes[1] == 1048576) {
        feat = (const float*)d_in[0];
        src  = (const int*)d_in[1];
        dst  = (const int*)d_in[2];
        degs = (const int*)d_in[3];
        W0 = (const float*)d_in[4];  b0 = (const float*)d_in[5];
        W1 = (const float*)d_in[6];  b1 = (const float*)d_in[7];
        W2 = (const float*)d_in[8];  b2 = (const float*)d_in[9];
        W3 = (const float*)d_in[10]; b3 = (const float*)d_in[11];
        cw1 = (const float*)d_in[12]; cb1 = (const float*)d_in[13];
        cw2 = (const float*)d_in[14]; cb2 = (const float*)d_in[15];
        ow  = (const float*)d_in[16]; ob  = (const float*)d_in[17];
    } else {
        feat = (const float*)d_in[0];
        W0 = (const float*)d_in[1];  b0 = (const float*)d_in[2];
        W1 = (const float*)d_in[3];  b1 = (const float*)d_in[4];
        W2 = (const float*)d_in[5];  b2 = (const float*)d_in[6];
        W3 = (const float*)d_in[7];  b3 = (const float*)d_in[8];
        cw1 = (const float*)d_in[9];  cb1 = (const float*)d_in[10];
        cw2 = (const float*)d_in[11]; cb2 = (const float*)d_in[12];
        ow  = (const float*)d_in[13]; ob  = (const float*)d_in[14];
        src  = (const int*)d_in[15];
        dst  = (const int*)d_in[16];
        degs = (const int*)d_in[17];
    }

    cudaFuncSetAttribute(dgcnn_kernel,
                         cudaFuncAttributeMaxDynamicSharedMemorySize, SMEM_TOTAL);
    dgcnn_kernel<<<256, 512, SMEM_TOTAL>>>(
        feat, src, dst, degs,
        W0, b0, W1, b1, W2, b2, W3, b3,
        cw1, cb1, cw2, cb2, ow, ob,
        (float*)d_out);
}

// round 5
// speedup vs baseline: 1.5341x; 1.3001x over previous
#include <cuda_runtime.h>
#include <stdint.h>

#define NPG  256
#define EPG  4096
#define KTOP 30
#define SA   36    // A stride (floats), 144B rows -> float4-aligned
#define SB   34    // B stride (floats)
#define SB2  17    // B stride in float2

// ---- dynamic smem layout (bytes) ----
#define OFF_A     0          // 256*36*4 = 36864
#define OFF_B     36864      // 256*34*4 = 34816
#define OFF_ACC   71680      // 16*256*4 = 16384 (aliases W0 during layer 0)
#define OFF_W0S   71680
#define OFF_CSR   88064      // 4096 u16 (entries = src*17)
#define OFF_W1    96256      // 1024 f32
#define OFF_W2    100352
#define OFF_CW1T  104448     // 97x16 f32
#define OFF_W3    110656     // 32 f32
#define OFF_B0    110784
#define OFF_B1    110912
#define OFF_B2    111040
#define OFF_B3    111168
#define OFF_DINV  111296     // 256 f32
#define OFF_COFF  112320     // 257 u32 (pad 1056)
#define OFF_CB1   113376     // 16 f32
#define SMEM_TOTAL 113440
// aliases inside B (early phase): CNT, WS. Late phase: KEYS.
#define OFF_CNT   OFF_B
#define OFF_WS    (OFF_B + 1024)
#define OFF_KEYS  OFF_B
// late-phase scratch inside A (A[0..255] holds h4)
#define SC_O1   1024
#define SC_PM   2944
#define SC_O2   3904
#define SC_CW2  5312
#define SC_OW   15552
#define SC_CB2  18368
#define SC_OB   18496

extern __shared__ unsigned char smem_raw[];

__device__ __forceinline__ void ffma2(float2& d, const float2 a, const float2 b) {
    asm("fma.rn.f32x2 %0, %1, %2, %0;"
        : "+l"(reinterpret_cast<unsigned long long&>(d))
        : "l"(reinterpret_cast<const unsigned long long&>(const_cast<float2&>(a))),
          "l"(reinterpret_cast<const unsigned long long&>(const_cast<float2&>(b))));
}
__device__ __forceinline__ void add2(float2& d, const float2 a) {
    asm("add.rn.f32x2 %0, %1, %0;"
        : "+l"(reinterpret_cast<unsigned long long&>(d))
        : "l"(reinterpret_cast<const unsigned long long&>(const_cast<float2&>(a))));
}
__device__ __forceinline__ float2 dup2(float a) { return make_float2(a, a); }

__device__ __forceinline__ float fast_tanh(float x) {
    x = fminf(fmaxf(x, -9.f), 9.f);
    float x2 = x * x;
    float p = fmaf(x2, -2.76076847742355e-16f, 2.00018790482477e-13f);
    p = fmaf(x2, p, -8.60467152213735e-11f);
    p = fmaf(x2, p, 5.12229709037114e-08f);
    p = fmaf(x2, p, 1.48572235717979e-05f);
    p = fmaf(x2, p, 6.37261928875436e-04f);
    p = fmaf(x2, p, 4.89352455891786e-03f);
    p *= x;
    float q = fmaf(x2, 1.19825839466702e-06f, 1.18534705686654e-04f);
    q = fmaf(x2, q, 2.26843463243900e-03f);
    q = fmaf(x2, q, 4.89352518554385e-03f);
    return __fdividef(p, q);
}

__device__ __forceinline__ int accidx(int c, int v) {
    return c * 256 + (v ^ ((c & 8) << 1));
}

// pooled = y[v] + sum_in y[src]; A[v] = tanh((pooled+b)*dinv).
// lanes: el = lane>>4 (edge slot), ch = lane&15 (channel pair). CSR2 = src*17.
__device__ __forceinline__ void scatter_act(const float* __restrict__ Bbuf,
                                            float* __restrict__ Abuf,
                                            const unsigned* __restrict__ OFFA,
                                            const unsigned short* __restrict__ CSR2,
                                            const float* __restrict__ bias,
                                            const float* __restrict__ dinv, int tid)
{
    int w = tid >> 5, lane = tid & 31;
    int el = lane >> 4, ch = lane & 15;
    const float2* B2 = (const float2*)Bbuf;
    float bl = bias[2 * ch + el];
    unsigned o1prev = OFFA[w * 16];
    for (int v = w * 16; v < w * 16 + 16; v++) {
        unsigned o0 = o1prev;
        unsigned o1 = OFFA[v + 1];
        o1prev = o1;
        float2 s0 = (el == 0) ? B2[v * SB2 + ch] : make_float2(0.f, 0.f);
        float2 s1 = make_float2(0.f, 0.f);
        unsigned i = o0 + (unsigned)el;
        while (i + 2 < o1) {
            unsigned a = CSR2[i], b = CSR2[i + 2];
            add2(s0, B2[a + ch]);
            add2(s1, B2[b + ch]);
            i += 4;
        }
        if (i < o1) add2(s0, B2[CSR2[i] + ch]);
        add2(s0, s1);
        float sx = s0.x + __shfl_xor_sync(0xffffffffu, s0.x, 16);
        float sy = s0.y + __shfl_xor_sync(0xffffffffu, s0.y, 16);
        float val = el ? sy : sx;
        Abuf[v * SA + 2 * ch + el] = fast_tanh((val + bl) * dinv[v]);
    }
}

// 256x32 @ 32x32: A (stride SA) -> B (stride SB). thread = (v=tid>>1, 16-col half)
__device__ __forceinline__ void gemm32_f2(const float* __restrict__ Ain,
                                          float* __restrict__ Bout,
                                          const float* __restrict__ Ws, int tid)
{
    int v = tid >> 1, half = tid & 1;
    const float4* ar4 = (const float4*)(Ain + v * SA);
    const float4* W4 = (const float4*)Ws;
    float2 acc[8];
#pragma unroll
    for (int j = 0; j < 8; j++) acc[j] = make_float2(0.f, 0.f);
#pragma unroll
    for (int k4 = 0; k4 < 8; k4++) {
        float4 a = ar4[k4];
        float av[4] = {a.x, a.y, a.z, a.w};
#pragma unroll
        for (int j = 0; j < 4; j++) {
            int k = k4 * 4 + j;
            float2 aa = dup2(av[j]);
#pragma unroll
            for (int q = 0; q < 4; q++) {
                float4 wv = W4[k * 8 + half * 4 + q];
                ffma2(acc[q * 2 + 0], aa, make_float2(wv.x, wv.y));
                ffma2(acc[q * 2 + 1], aa, make_float2(wv.z, wv.w));
            }
        }
    }
    float2* o = (float2*)Bout + v * SB2 + half * 8;
#pragma unroll
    for (int j = 0; j < 8; j++) o[j] = acc[j];
}

// ACC[c][v] (+)= dot(A[v,0:32], w[k][c]) for c in half*8..+8
__device__ __forceinline__ void acc_pass(const float* __restrict__ Ain,
                                         float* __restrict__ ACC,
                                         const float* __restrict__ w, // [32][16]
                                         int tid, bool first)
{
    int v = tid >> 1, half = tid & 1;
    const float4* ar4 = (const float4*)(Ain + v * SA);
    float2 a0 = make_float2(0.f, 0.f), a1 = a0, a2 = a0, a3 = a0;
#pragma unroll
    for (int k4 = 0; k4 < 8; k4++) {
        float4 a = ar4[k4];
        float av[4] = {a.x, a.y, a.z, a.w};
#pragma unroll
        for (int j = 0; j < 4; j++) {
            int k = k4 * 4 + j;
            float2 aa = dup2(av[j]);
            float4 w0 = *(const float4*)(w + k * 16 + half * 8);
            float4 w1 = *(const float4*)(w + k * 16 + half * 8 + 4);
            ffma2(a0, aa, make_float2(w0.x, w0.y));
            ffma2(a1, aa, make_float2(w0.z, w0.w));
            ffma2(a2, aa, make_float2(w1.x, w1.y));
            ffma2(a3, aa, make_float2(w1.z, w1.w));
        }
    }
    float r[8] = {a0.x, a0.y, a1.x, a1.y, a2.x, a2.y, a3.x, a3.y};
    int cb = half * 8;
    if (first) {
#pragma unroll
        for (int j = 0; j < 8; j++) ACC[accidx(cb + j, v)] = r[j];
    } else {
#pragma unroll
        for (int j = 0; j < 8; j++) ACC[accidx(cb + j, v)] += r[j];
    }
}

__global__ void __launch_bounds__(512, 2)
dgcnn_kernel(const float* __restrict__ feat,
             const int* __restrict__ src, const int* __restrict__ dst,
             const int* __restrict__ degs,
             const float* __restrict__ W0, const float* __restrict__ b0,
             const float* __restrict__ W1, const float* __restrict__ b1,
             const float* __restrict__ W2, const float* __restrict__ b2,
             const float* __restrict__ W3, const float* __restrict__ b3,
             const float* __restrict__ cw1, const float* __restrict__ cb1,
             const float* __restrict__ cw2, const float* __restrict__ cb2,
             const float* __restrict__ ow, const float* __restrict__ ob,
             float* __restrict__ out)
{
    const int g   = blockIdx.x;
    const int tid = threadIdx.x;

    float* A   = (float*)(smem_raw + OFF_A);
    float* B   = (float*)(smem_raw + OFF_B);
    float* ACC = (float*)(smem_raw + OFF_ACC);
    float* W0s = (float*)(smem_raw + OFF_W0S);
    unsigned short* CSR2 = (unsigned short*)(smem_raw + OFF_CSR);
    float* W1s = (float*)(smem_raw + OFF_W1);
    float* W2s = (float*)(smem_raw + OFF_W2);
    float* CW1T = (float*)(smem_raw + OFF_CW1T);
    float* W3s = (float*)(smem_raw + OFF_W3);
    float* B0s = (float*)(smem_raw + OFF_B0);
    float* B1s = (float*)(smem_raw + OFF_B1);
    float* B2s = (float*)(smem_raw + OFF_B2);
    float* B3s = (float*)(smem_raw + OFF_B3);
    float* DINV = (float*)(smem_raw + OFF_DINV);
    unsigned* COFF = (unsigned*)(smem_raw + OFF_COFF);
    unsigned* CNT  = (unsigned*)(smem_raw + OFF_CNT);
    unsigned* WS   = (unsigned*)(smem_raw + OFF_WS);
    unsigned long long* KEYS = (unsigned long long*)(smem_raw + OFF_KEYS);
    float* CB1s = (float*)(smem_raw + OFF_CB1);
    float* O1s  = (float*)(smem_raw + OFF_A + SC_O1);
    float* PMs  = (float*)(smem_raw + OFF_A + SC_PM);
    float* O2s  = (float*)(smem_raw + OFF_A + SC_O2);
    float* CW2c = (float*)(smem_raw + OFF_A + SC_CW2);
    float* OWc  = (float*)(smem_raw + OFF_A + SC_OW);
    float* CB2c = (float*)(smem_raw + OFF_A + SC_CB2);
    float* OBc  = (float*)(smem_raw + OFF_A + SC_OB);

    // ---- Phase A: weights, degs, scan, CSR ----
    for (int i = tid; i < 256; i += 512) {
        ((float4*)W1s)[i] = ((const float4*)W1)[i];
        ((float4*)W2s)[i] = ((const float4*)W2)[i];
    }
    for (int i = tid; i < 1024; i += 512) ((float4*)W0s)[i] = ((const float4*)W0)[i];
    for (int i = tid; i < 97 * 16; i += 512) {
        int d = i >> 4, c = i & 15;
        CW1T[i] = cw1[c * 97 + d];
    }
    if (tid < 32) { W3s[tid] = W3[tid]; B0s[tid] = b0[tid]; B1s[tid] = b1[tid]; B2s[tid] = b2[tid]; }
    if (tid == 0) B3s[0] = b3[0];
    if (tid < 16) CB1s[tid] = cb1[tid];

    int indeg = 0;
    unsigned xincl = 0;
    if (tid < 256) {
        indeg = degs[g * NPG + tid];
        DINV[tid] = 1.0f / (float)(indeg + 1);
        CNT[tid]  = 0u;
        xincl = (unsigned)indeg;
#pragma unroll
        for (int d = 1; d < 32; d <<= 1) {
            unsigned t = __shfl_up_sync(0xffffffffu, xincl, d);
            if ((tid & 31) >= d) xincl += t;
        }
        if ((tid & 31) == 31) WS[tid >> 5] = xincl;
    }
    __syncthreads();
    if (tid == 0) {
        unsigned run = 0;
#pragma unroll
        for (int w = 0; w < 8; w++) { unsigned t = WS[w]; WS[w] = run; run += t; }
    }
    __syncthreads();
    if (tid < 256) COFF[tid] = xincl + WS[tid >> 5] - (unsigned)indeg;
    if (tid == 0) COFF[256] = EPG;
    __syncthreads();

    {
        const int gbase = g * NPG;
        const int4* s4 = (const int4*)(src + g * EPG);
        const int4* d4 = (const int4*)(dst + g * EPG);
        for (int e = tid; e < EPG / 4; e += 512) {
            int4 S = s4[e], D = d4[e];
            { int dl = D.x - gbase; unsigned p = atomicAdd(&CNT[dl], 1u);
              CSR2[COFF[dl] + p] = (unsigned short)((S.x - gbase) * SB2); }
            { int dl = D.y - gbase; unsigned p = atomicAdd(&CNT[dl], 1u);
              CSR2[COFF[dl] + p] = (unsigned short)((S.y - gbase) * SB2); }
            { int dl = D.z - gbase; unsigned p = atomicAdd(&CNT[dl], 1u);
              CSR2[COFF[dl] + p] = (unsigned short)((S.z - gbase) * SB2); }
            { int dl = D.w - gbase; unsigned p = atomicAdd(&CNT[dl], 1u);
              CSR2[COFF[dl] + p] = (unsigned short)((S.w - gbase) * SB2); }
        }
    }
    __syncthreads();   // CSR + W0s ready; B (CNT alias) now dead

    // ---- layer 0 GEMM directly from GMEM: feat[256x128] @ W0 -> B ----
    {
        int rp = tid >> 2;     // 0..127 -> rows 2rp, 2rp+1
        int cg = tid & 3;      // cols cg*8 .. cg*8+7
        const float4* a0p = (const float4*)(feat + ((size_t)(g * NPG) + 2 * rp) * 128);
        const float4* a1p = a0p + 32;
        const float4* W04 = (const float4*)W0s;
        float2 acc[8];
#pragma unroll
        for (int j = 0; j < 8; j++) acc[j] = make_float2(0.f, 0.f);
        float4 a0c = a0p[0], a1c = a1p[0];
#pragma unroll 4
        for (int k4 = 0; k4 < 32; k4++) {
            float4 a0n = a0c, a1n = a1c;
            if (k4 < 31) { a0n = a0p[k4 + 1]; a1n = a1p[k4 + 1]; }
            float av0[4] = {a0c.x, a0c.y, a0c.z, a0c.w};
            float av1[4] = {a1c.x, a1c.y, a1c.z, a1c.w};
#pragma unroll
            for (int j = 0; j < 4; j++) {
                int k = k4 * 4 + j;
                float4 w0 = W04[k * 8 + cg * 2];
                float4 w1 = W04[k * 8 + cg * 2 + 1];
                float2 r0 = dup2(av0[j]), r1 = dup2(av1[j]);
                ffma2(acc[0], r0, make_float2(w0.x, w0.y));
                ffma2(acc[1], r0, make_float2(w0.z, w0.w));
                ffma2(acc[2], r0, make_float2(w1.x, w1.y));
                ffma2(acc[3], r0, make_float2(w1.z, w1.w));
                ffma2(acc[4], r1, make_float2(w0.x, w0.y));
                ffma2(acc[5], r1, make_float2(w0.z, w0.w));
                ffma2(acc[6], r1, make_float2(w1.x, w1.y));
                ffma2(acc[7], r1, make_float2(w1.z, w1.w));
            }
            a0c = a0n; a1c = a1n;
        }
        float4* st0 = (float4*)(B + 2 * rp * SB + cg * 8);
        st0[0] = make_float4(acc[0].x, acc[0].y, acc[1].x, acc[1].y);
        st0[1] = make_float4(acc[2].x, acc[2].y, acc[3].x, acc[3].y);
        float2* st1 = (float2*)(B + (2 * rp + 1) * SB + cg * 8);
        st1[0] = acc[4]; st1[1] = acc[5]; st1[2] = acc[6]; st1[3] = acc[7];
    }
    __syncthreads();

    // ---- GNN layers ----
    scatter_act(B, A, COFF, CSR2, B0s, DINV, tid);
    __syncwarp();
    acc_pass(A, ACC, CW1T, tid, true);
    __syncthreads();
    gemm32_f2(A, B, W1s, tid);
    __syncthreads();
    scatter_act(B, A, COFF, CSR2, B1s, DINV, tid);
    __syncwarp();
    acc_pass(A, ACC, CW1T + 32 * 16, tid, false);
    __syncthreads();
    gemm32_f2(A, B, W2s, tid);
    __syncthreads();
    scatter_act(B, A, COFF, CSR2, B2s, DINV, tid);
    __syncwarp();
    acc_pass(A, ACC, CW1T + 64 * 16, tid, false);
    __syncthreads();

    // layer 3 (dout=1): y3 -> B[v*SB]
    if (tid < 256) {
        const float4* zr4 = (const float4*)(A + tid * SA);
        float s0 = 0.f, s1 = 0.f, s2 = 0.f, s3 = 0.f;
#pragma unroll
        for (int q = 0; q < 8; q++) {
            float4 z = zr4[q];
            s0 = fmaf(z.x, W3s[4 * q],     s0);
            s1 = fmaf(z.y, W3s[4 * q + 1], s1);
            s2 = fmaf(z.z, W3s[4 * q + 2], s2);
            s3 = fmaf(z.w, W3s[4 * q + 3], s3);
        }
        B[tid * SB] = (s0 + s1) + (s2 + s3);
    }
    __syncthreads();
    // h4 -> A[0..255]
    if (tid < 256) {
        unsigned o0 = COFF[tid], o1 = COFF[tid + 1];
        float s0 = B[tid * SB], s1 = 0.f, s2 = 0.f, s3 = 0.f;
        unsigned i = o0;
        for (; i + 4 <= o1; i += 4) {
            unsigned a = CSR2[i], b = CSR2[i + 1], c = CSR2[i + 2], d = CSR2[i + 3];
            s0 += B[a * 2]; s1 += B[b * 2]; s2 += B[c * 2]; s3 += B[d * 2];
        }
        for (; i < o1; i++) s0 += B[CSR2[i] * 2];
        A[tid] = fast_tanh(((s0 + s1) + (s2 + s3) + B3s[0]) * DINV[tid]);
    }
    __syncthreads();   // B dead -> KEYS region

    // keys (warps 0-7) + CNN-head weight staging (warps 8-15)
    if (tid < 256) {
        unsigned bits = __float_as_uint(A[tid]);
        unsigned uv = (bits & 0x80000000u) ? ~bits : (bits | 0x80000000u);
        KEYS[tid] = ((unsigned long long)(~uv) << 32) | (unsigned)tid;
    } else {
        int t = tid - 256;
        for (int i = t; i < 640; i += 256) ((float4*)CW2c)[i] = ((const float4*)cw2)[i];
        for (int i = t; i < 176; i += 256) ((float4*)OWc)[i] = ((const float4*)ow)[i];
        if (t < 32) CB2c[t] = cb2[t];
        if (t < 2) OBc[t] = ob[t];
    }
    __syncthreads();

    // bitonic sort 256 u64 keys (warps 0-7 only, named barrier)
    if (tid < 256) {
        for (int k = 2; k <= 256; k <<= 1) {
            for (int j = k >> 1; j > 0; j >>= 1) {
                int ixj = tid ^ j;
                if (ixj > tid) {
                    bool up = ((tid & k) == 0);
                    unsigned long long a = KEYS[tid], b = KEYS[ixj];
                    if ((a > b) == up) { KEYS[tid] = b; KEYS[ixj] = a; }
                }
                asm volatile("bar.sync 1, 256;" ::: "memory");
            }
        }
    }
    __syncthreads();

    // conv1 from ACC (+ h4 term), relu
    if (tid < 480) {
        int c = tid & 15, k = tid >> 4;
        int idx = (int)(KEYS[k] & 0xFFu);
        float s = ACC[accidx(c, idx)] + A[idx] * CW1T[96 * 16 + c] + CB1s[c];
        O1s[c * KTOP + k] = fmaxf(s, 0.f);
    }
    __syncthreads();
    for (int t = tid; t < 16 * 15; t += 512) {
        int c = t / 15, j = t % 15;
        PMs[c * 15 + j] = fmaxf(O1s[c * KTOP + 2 * j], O1s[c * KTOP + 2 * j + 1]);
    }
    __syncthreads();
    for (int t = tid; t < 32 * 11; t += 512) {
        int c2 = t / 11, tt = t % 11;
        float s = CB2c[c2];
#pragma unroll 4
        for (int c1 = 0; c1 < 16; c1++) {
            const float* w = CW2c + (c2 * 16 + c1) * 5;
            const float* p = PMs + c1 * 15 + tt;
#pragma unroll
            for (int kk = 0; kk < 5; kk++) s = fmaf(p[kk], w[kk], s);
        }
        O2s[c2 * 11 + tt] = fmaxf(s, 0.f);
    }
    __syncthreads();
    if (tid < 64) {
        int o = tid >> 5, lane = tid & 31;
        float s = 0.f;
        for (int i = lane; i < 352; i += 32) s = fmaf(O2s[i], OWc[i * 2 + o], s);
#pragma unroll
        for (int d = 16; d > 0; d >>= 1) s += __shfl_down_sync(0xffffffffu, s, d);
        if (lane == 0) out[g * 2 + o] = fmaxf(s + OBc[o], 0.f);
    }
}

extern "C" void kernel_launch(void* const* d_in, const int* in_sizes, int n_in,
                              void* d_out, int out_size)
{
    const float *feat, *W0, *b0, *W1, *b1, *W2, *b2, *W3, *b3;
    const float *cw1, *cb1, *cw2, *cb2, *ow, *ob;
    const int *src, *dst, *degs;

    if (n_in >= 2 && in_sizes[1] == 1048576) {
        feat = (const float*)d_in[0];
        src  = (const int*)d_in[1];
        dst  = (const int*)d_in[2];
        degs = (const int*)d_in[3];
        W0 = (const float*)d_in[4];  b0 = (const float*)d_in[5];
        W1 = (const float*)d_in[6];  b1 = (const float*)d_in[7];
        W2 = (const float*)d_in[8];  b2 = (const float*)d_in[9];
        W3 = (const float*)d_in[10]; b3 = (const float*)d_in[11];
        cw1 = (const float*)d_in[12]; cb1 = (const float*)d_in[13];
        cw2 = (const float*)d_in[14]; cb2 = (const float*)d_in[15];
        ow  = (const float*)d_in[16]; ob  = (const float*)d_in[17];
    } else {
        feat = (const float*)d_in[0];
        W0 = (const float*)d_in[1];  b0 = (const float*)d_in[2];
        W1 = (const float*)d_in[3];  b1 = (const float*)d_in[4];
        W2 = (const float*)d_in[5];  b2 = (const float*)d_in[6];
        W3 = (const float*)d_in[7];  b3 = (const float*)d_in[8];
        cw1 = (const float*)d_in[9];  cb1 = (const float*)d_in[10];
        cw2 = (const float*)d_in[11]; cb2 = (const float*)d_in[12];
        ow  = (const float*)d_in[13]; ob  = (const float*)d_in[14];
        src  = (const int*)d_in[15];
        dst  = (const int*)d_in[16];
        degs = (const int*)d_in[17];
    }

    cudaFuncSetAttribute(dgcnn_kernel,
                         cudaFuncAttributeMaxDynamicSharedMemorySize, SMEM_TOTAL);
    dgcnn_kernel<<<256, 512, SMEM_TOTAL>>>(
        feat, src, dst, degs,
        W0, b0, W1, b1, W2, b2, W3, b3,
        cw1, cb1, cw2, cb2, ow, ob,
        (float*)d_out);
}